// round 17
// baseline (speedup 1.0000x reference)
#include <cuda_runtime.h>
#include <cuda_bf16.h>
#include <mma.h>
#include <math.h>
#include <stdint.h>

using namespace nvcuda;

#define TOKS    8192
#define DMODEL  1024
#define FEXP    512
#define NEXP    16
#define NROUTED 14
#define KROUTE  4
#define KSEL    6

#define BM 128
#define BN 64
#define BK 32
#define LDA 40       // A smem row stride (32 + 8 pad) elems
#define LDB 72       // B smem row stride (64 + 8 pad) elems
#define NSTAGE 3

// ---------------- device scratch ---------------------------------------------
__device__ __align__(16) int   g_cnt[NEXP];
__device__ int   g_ok1, g_ok2;
__device__ __align__(16) int   g_tok[NEXP * TOKS];
__device__ __align__(16) int   g_slot[TOKS * KSEL];
__device__ __align__(16) float g_aff[NEXP * TOKS];

__device__ __align__(16) __nv_bfloat16 g_x_hi[(size_t)TOKS * DMODEL];
__device__ __align__(16) __nv_bfloat16 g_x_lo[(size_t)TOKS * DMODEL];
__device__ __align__(16) __nv_bfloat16 g_k_hi[(size_t)NEXP * DMODEL * FEXP];
__device__ __align__(16) __nv_bfloat16 g_k_lo[(size_t)NEXP * DMODEL * FEXP];
__device__ __align__(16) __nv_bfloat16 g_v_hi[(size_t)NEXP * FEXP * DMODEL];
__device__ __align__(16) __nv_bfloat16 g_v_lo[(size_t)NEXP * FEXP * DMODEL];
__device__ __align__(16) __nv_bfloat16 g_h_hi[(size_t)NEXP * TOKS * FEXP];
__device__ __align__(16) __nv_bfloat16 g_h_lo[(size_t)NEXP * TOKS * FEXP];
__device__ __align__(16) float g_hf[(size_t)NEXP * TOKS * FEXP];     // fb H (fp32)
__device__ __align__(16) float g_out_tc[(size_t)TOKS * DMODEL];      // TC accum

// ---------------- helpers ----------------------------------------------------
__device__ __forceinline__ unsigned short bf16bits(float f) {
    __nv_bfloat16 b = __float2bfloat16(f);
    return *reinterpret_cast<unsigned short*>(&b);
}
__device__ __forceinline__ float bf16val(unsigned short u) {
    __nv_bfloat16 b = *reinterpret_cast<__nv_bfloat16*>(&u);
    return __bfloat162float(b);
}
__device__ __forceinline__ uint32_t smem_u32(const void* p) {
    uint32_t a;
    asm("{ .reg .u64 t; cvta.to.shared.u64 t, %1; cvt.u32.u64 %0, t; }" : "=r"(a) : "l"(p));
    return a;
}
__device__ __forceinline__ void cp_async16(uint32_t dst, const void* src) {
    asm volatile("cp.async.cg.shared.global [%0], [%1], 16;" :: "r"(dst), "l"(src));
}
__device__ __forceinline__ void cp_commit() { asm volatile("cp.async.commit_group;"); }
__device__ __forceinline__ void cp_wait1()  { asm volatile("cp.async.wait_group 1;"); }
__device__ __forceinline__ void cp_wait0()  { asm volatile("cp.async.wait_group 0;"); }

// dynamic-smem tile block (one pipeline stage)
struct __align__(16) Tiles {
    __nv_bfloat16 a_hi[BM * LDA];   // 10240 B
    __nv_bfloat16 a_lo[BM * LDA];   // 10240 B
    __nv_bfloat16 b_hi[BK * LDB];   //  4608 B
    __nv_bfloat16 b_lo[BK * LDB];   //  4608 B
};                                   // 29696 B
#define SMEM_GEMM (1024 + NSTAGE * (int)sizeof(Tiles))   // 90112

// ---------------- utility kernels -------------------------------------------
__global__ void zero_out_kernel(float* out, int n) {
    int i = blockIdx.x * blockDim.x + threadIdx.x;
    if (i < n) out[i] = 0.f;
}
__global__ void zero_misc_kernel() {
    if (threadIdx.x < NEXP) g_cnt[threadIdx.x] = 0;
    if (threadIdx.x == 0) { g_ok1 = 1; g_ok2 = 1; }
}
__global__ void zero_tc_kernel() {
    int i = blockIdx.x * blockDim.x + threadIdx.x;
    if (i < TOKS * DMODEL) g_out_tc[i] = 0.f;
}

// elementwise fp32 -> bf16 hi/lo split (layout-preserving)
__global__ __launch_bounds__(256) void conv_split_kernel(
    const float* __restrict__ src, __nv_bfloat16* __restrict__ dhi,
    __nv_bfloat16* __restrict__ dlo, int n4)
{
    int i = blockIdx.x * blockDim.x + threadIdx.x;
    if (i >= n4) return;
    float4 v = reinterpret_cast<const float4*>(src)[i];
    ushort4 h, l;
    h.x = bf16bits(v.x); l.x = bf16bits(v.x - bf16val(h.x));
    h.y = bf16bits(v.y); l.y = bf16bits(v.y - bf16val(h.y));
    h.z = bf16bits(v.z); l.z = bf16bits(v.z - bf16val(h.z));
    h.w = bf16bits(v.w); l.w = bf16bits(v.w - bf16val(h.w));
    reinterpret_cast<ushort4*>(dhi)[i] = h;
    reinterpret_cast<ushort4*>(dlo)[i] = l;
}

// ---------------- routing ---------------------------------------------------
__global__ __launch_bounds__(256) void routing_kernel(
    const float* __restrict__ sel_in,
    const float* __restrict__ expert_sel,
    const float* __restrict__ bias,
    float* __restrict__ out, int write_sel)
{
    const int t    = blockIdx.x;
    const int tid  = threadIdx.x;
    const int warp = tid >> 5, lane = tid & 31;
    __shared__ float logit[NEXP];

    const float* x = sel_in + (size_t)t * DMODEL;
    #pragma unroll
    for (int w = 0; w < 2; w++) {
        int e = warp * 2 + w;
        const float* wr = expert_sel + (size_t)e * DMODEL;
        float s = 0.f;
        for (int i = lane; i < DMODEL; i += 32) s += x[i] * wr[i];
        #pragma unroll
        for (int o = 16; o > 0; o >>= 1) s += __shfl_xor_sync(0xffffffffu, s, o);
        if (lane == 0) logit[e] = s;
    }
    __syncthreads();

    if (tid == 0) {
        float a[NEXP];
        #pragma unroll
        for (int e = 0; e < NEXP; e++) a[e] = 1.f / (1.f + expf(-logit[e]));

        int sel[KSEL]; float af[KSEL];
        bool taken[NROUTED];
        #pragma unroll
        for (int i = 0; i < NROUTED; i++) taken[i] = false;
        #pragma unroll
        for (int k = 0; k < KROUTE; k++) {
            float best = -1e30f; int bi = 0;
            for (int i = 0; i < NROUTED; i++) {
                float v = a[i] + bias[i];
                if (!taken[i] && v > best) { best = v; bi = i; }
            }
            taken[bi] = true; sel[k] = bi; af[k] = a[bi];
        }
        sel[4] = NROUTED;     af[4] = a[NROUTED];
        sel[5] = NROUTED + 1; af[5] = a[NROUTED + 1];

        #pragma unroll
        for (int k = 0; k < KSEL; k++) {
            int e   = sel[k];
            int pos = atomicAdd(&g_cnt[e], 1);
            g_tok[e * TOKS + pos] = t;
            g_aff[e * TOKS + pos] = af[k];
            g_slot[t * KSEL + k] = pos;
            if (write_sel)
                out[(size_t)TOKS * DMODEL + (size_t)t * KSEL + k] = (float)e;
        }
    }
}

// ---------------- 3-term wmma over one BK=32 chunk (R12-verified) -----------
__device__ __forceinline__ void mma_stage(
    const Tiles& t, int wm, int wn,
    wmma::fragment<wmma::accumulator, 16, 16, 16, float> (&acc)[2][2])
{
    wmma::fragment<wmma::matrix_a, 16, 16, 16, __nv_bfloat16, wmma::row_major> fa_hi, fa_lo;
    wmma::fragment<wmma::matrix_b, 16, 16, 16, __nv_bfloat16, wmma::row_major> fb_hi[2], fb_lo[2];
    #pragma unroll
    for (int ks = 0; ks < BK; ks += 16) {
        #pragma unroll
        for (int nt = 0; nt < 2; nt++) {
            wmma::load_matrix_sync(fb_hi[nt], &t.b_hi[ks * LDB + wn + nt * 16], LDB);
            wmma::load_matrix_sync(fb_lo[nt], &t.b_lo[ks * LDB + wn + nt * 16], LDB);
        }
        #pragma unroll
        for (int mt = 0; mt < 2; mt++) {
            wmma::load_matrix_sync(fa_hi, &t.a_hi[(wm + mt * 16) * LDA + ks], LDA);
            wmma::load_matrix_sync(fa_lo, &t.a_lo[(wm + mt * 16) * LDA + ks], LDA);
            #pragma unroll
            for (int nt = 0; nt < 2; nt++) {
                wmma::mma_sync(acc[mt][nt], fa_hi, fb_hi[nt], acc[mt][nt]);
                wmma::mma_sync(acc[mt][nt], fa_hi, fb_lo[nt], acc[mt][nt]);
                wmma::mma_sync(acc[mt][nt], fa_lo, fb_hi[nt], acc[mt][nt]);
            }
        }
    }
}

// cp.async one stage: A 1024 granules + B 512 granules, 16B each
__device__ __forceinline__ void issue_stage_g1(
    Tiles* stg, const int* toks, int e, int n0, int k0, int tid)
{
    uint32_t base = smem_u32(stg);
    #pragma unroll
    for (int it = 0; it < 4; it++) {              // A
        int idx = tid + it * 256;
        int h = idx >> 9, rr = (idx >> 2) & 127, q = idx & 3;
        const __nv_bfloat16* src = (h ? g_x_lo : g_x_hi)
            + (size_t)toks[rr] * DMODEL + k0 + q * 8;
        cp_async16(base + (uint32_t)(h * BM * LDA + rr * LDA + q * 8) * 2u, src);
    }
    #pragma unroll
    for (int it = 0; it < 2; it++) {              // B
        int idx = tid + it * 256;
        int h = idx >> 8, rr = (idx >> 3) & 31, g = idx & 7;
        const __nv_bfloat16* src = (h ? g_k_lo : g_k_hi)
            + ((size_t)e * DMODEL + k0 + rr) * FEXP + n0 + g * 8;
        cp_async16(base + (uint32_t)(2 * BM * LDA + h * BK * LDB + rr * LDB + g * 8) * 2u, src);
    }
}
__device__ __forceinline__ void issue_stage_g2(
    Tiles* stg, int e, int m0, int n0, int k0, int tid)
{
    uint32_t base = smem_u32(stg);
    #pragma unroll
    for (int it = 0; it < 4; it++) {              // A (bf16 H)
        int idx = tid + it * 256;
        int h = idx >> 9, rr = (idx >> 2) & 127, q = idx & 3;
        const __nv_bfloat16* src = (h ? g_h_lo : g_h_hi)
            + ((size_t)e * TOKS + m0 + rr) * FEXP + k0 + q * 8;
        cp_async16(base + (uint32_t)(h * BM * LDA + rr * LDA + q * 8) * 2u, src);
    }
    #pragma unroll
    for (int it = 0; it < 2; it++) {              // B (values)
        int idx = tid + it * 256;
        int h = idx >> 8, rr = (idx >> 3) & 31, g = idx & 7;
        const __nv_bfloat16* src = (h ? g_v_lo : g_v_hi)
            + ((size_t)e * FEXP + k0 + rr) * DMODEL + n0 + g * 8;
        cp_async16(base + (uint32_t)(2 * BM * LDA + h * BK * LDB + rr * LDB + g * 8) * 2u, src);
    }
}

// GEMM1: H[slot][f] = silu( x[tok] @ keys[e] )[f] * aff -> bf16 hi/lo
__global__ __launch_bounds__(256, 2) void moe_gemm1() {
    const int e   = blockIdx.y;
    const int cnt = g_cnt[e];
    const int m0  = blockIdx.x * BM;
    if (m0 >= cnt) return;
    const int n0  = blockIdx.z * BN;

    extern __shared__ char smem_raw[];
    int*   toks = (int*)smem_raw;
    float* affs = (float*)(smem_raw + 512);
    Tiles* st   = (Tiles*)(smem_raw + 1024);
    float* epi  = (float*)(smem_raw + 1024);

    const int tid = threadIdx.x, w = tid >> 5, lane = tid & 31;
    const int wm = (w >> 1) * 32, wn = (w & 1) * 32;

    if (tid < BM) {
        int mg = m0 + tid; bool v = mg < cnt;
        toks[tid] = v ? g_tok[e * TOKS + mg] : 0;
        affs[tid] = v ? g_aff[e * TOKS + mg] : 0.f;
    }
    __syncthreads();

    wmma::fragment<wmma::accumulator, 16, 16, 16, float> acc[2][2];
    #pragma unroll
    for (int i = 0; i < 2; i++)
        #pragma unroll
        for (int j = 0; j < 2; j++) wmma::fill_fragment(acc[i][j], 0.f);

    const int NC = DMODEL / BK;    // 32
    issue_stage_g1(&st[0], toks, e, n0, 0, tid);  cp_commit();
    issue_stage_g1(&st[1], toks, e, n0, BK, tid); cp_commit();

    for (int c = 0; c < NC; c++) {
        if (c < NC - 1) cp_wait1(); else cp_wait0();
        __syncthreads();
        if (c + 2 < NC) {
            issue_stage_g1(&st[(c + 2) % NSTAGE], toks, e, n0, (c + 2) * BK, tid);
            cp_commit();
        }
        mma_stage(st[c % NSTAGE], wm, wn, acc);
    }
    __syncthreads();   // all mma reads done before epi overlays tiles

    float* ep = epi + w * 1024;
    #pragma unroll
    for (int mt = 0; mt < 2; mt++)
        #pragma unroll
        for (int nt = 0; nt < 2; nt++)
            wmma::store_matrix_sync(ep + (mt * 2 + nt) * 256, acc[mt][nt], 16,
                                    wmma::mem_row_major);
    __syncwarp();

    const int mloc = wm + lane;
    const int mt = lane >> 4, lr = lane & 15;
    if (m0 + mloc < cnt) {
        float aff = affs[mloc];
        size_t rowb = ((size_t)e * TOKS + m0 + mloc) * FEXP + n0 + wn;
        unsigned short* dh = reinterpret_cast<unsigned short*>(g_h_hi) + rowb;
        unsigned short* dl = reinterpret_cast<unsigned short*>(g_h_lo) + rowb;
        #pragma unroll
        for (int nt = 0; nt < 2; nt++) {
            #pragma unroll
            for (int p = 0; p < 16; p += 2) {
                float v0 = ep[(mt * 2 + nt) * 256 + lr * 16 + p];
                float v1 = ep[(mt * 2 + nt) * 256 + lr * 16 + p + 1];
                float h0 = v0 / (1.f + __expf(-v0)) * aff;
                float h1 = v1 / (1.f + __expf(-v1)) * aff;
                unsigned short hb0 = bf16bits(h0), hb1 = bf16bits(h1);
                unsigned short lb0 = bf16bits(h0 - bf16val(hb0));
                unsigned short lb1 = bf16bits(h1 - bf16val(hb1));
                *reinterpret_cast<uint32_t*>(dh + nt * 16 + p)
                    = (uint32_t)hb0 | ((uint32_t)hb1 << 16);
                *reinterpret_cast<uint32_t*>(dl + nt * 16 + p)
                    = (uint32_t)lb0 | ((uint32_t)lb1 << 16);
            }
        }
    }
}

// GEMM2: g_out_tc[tok][d] += H[slot] @ values[e]
__global__ __launch_bounds__(256, 2) void moe_gemm2() {
    const int e   = blockIdx.y;
    const int cnt = g_cnt[e];
    const int m0  = blockIdx.x * BM;
    if (m0 >= cnt) return;
    const int n0  = blockIdx.z * BN;

    extern __shared__ char smem_raw[];
    int*   toks = (int*)smem_raw;
    Tiles* st   = (Tiles*)(smem_raw + 1024);
    float* epi  = (float*)(smem_raw + 1024);

    const int tid = threadIdx.x, w = tid >> 5, lane = tid & 31;
    const int wm = (w >> 1) * 32, wn = (w & 1) * 32;

    if (tid < BM) {
        int mg = m0 + tid;
        toks[tid] = (mg < cnt) ? g_tok[e * TOKS + mg] : 0;
    }
    __syncthreads();

    wmma::fragment<wmma::accumulator, 16, 16, 16, float> acc[2][2];
    #pragma unroll
    for (int i = 0; i < 2; i++)
        #pragma unroll
        for (int j = 0; j < 2; j++) wmma::fill_fragment(acc[i][j], 0.f);

    const int NC = FEXP / BK;    // 16
    issue_stage_g2(&st[0], e, m0, n0, 0, tid);  cp_commit();
    issue_stage_g2(&st[1], e, m0, n0, BK, tid); cp_commit();

    for (int c = 0; c < NC; c++) {
        if (c < NC - 1) cp_wait1(); else cp_wait0();
        __syncthreads();
        if (c + 2 < NC) {
            issue_stage_g2(&st[(c + 2) % NSTAGE], e, m0, n0, (c + 2) * BK, tid);
            cp_commit();
        }
        mma_stage(st[c % NSTAGE], wm, wn, acc);
    }
    __syncthreads();

    float* ep = epi + w * 1024;
    #pragma unroll
    for (int mt = 0; mt < 2; mt++)
        #pragma unroll
        for (int nt = 0; nt < 2; nt++)
            wmma::store_matrix_sync(ep + (mt * 2 + nt) * 256, acc[mt][nt], 16,
                                    wmma::mem_row_major);
    __syncwarp();

    const int mloc = wm + lane;
    const int mt = lane >> 4, lr = lane & 15;
    if (m0 + mloc < cnt) {
        float* dst = g_out_tc + (size_t)toks[mloc] * DMODEL + n0 + wn;
        #pragma unroll
        for (int nt = 0; nt < 2; nt++)
            #pragma unroll
            for (int p = 0; p < 16; p++)
                atomicAdd(dst + nt * 16 + p, ep[(mt * 2 + nt) * 256 + lr * 16 + p]);
    }
}

// ---------------- lightweight verify on 4 probe tokens -----------------------
__global__ __launch_bounds__(256) void verify_kernel(
    const float* __restrict__ x, const float* __restrict__ sel_in,
    const float* __restrict__ keys, const float* __restrict__ values,
    const float* __restrict__ expert_sel, const float* __restrict__ bias)
{
    const int t   = (blockIdx.x * 2731 + 17) & (TOKS - 1);
    const int tid = threadIdx.x;
    const int warp = tid >> 5, lane = tid & 31;
    __shared__ float logit[NEXP];
    __shared__ int   sel[KSEL];
    __shared__ float aff[KSEL];

    const float* xs = sel_in + (size_t)t * DMODEL;
    #pragma unroll
    for (int w = 0; w < 2; w++) {
        int e = warp * 2 + w;
        const float* wr = expert_sel + (size_t)e * DMODEL;
        float s = 0.f;
        for (int i = lane; i < DMODEL; i += 32) s += xs[i] * wr[i];
        #pragma unroll
        for (int o = 16; o > 0; o >>= 1) s += __shfl_xor_sync(0xffffffffu, s, o);
        if (lane == 0) logit[e] = s;
    }
    __syncthreads();

    if (tid == 0) {
        float a[NEXP];
        #pragma unroll
        for (int e = 0; e < NEXP; e++) a[e] = 1.f / (1.f + expf(-logit[e]));
        bool taken[NROUTED];
        #pragma unroll
        for (int i = 0; i < NROUTED; i++) taken[i] = false;
        #pragma unroll
        for (int k = 0; k < KROUTE; k++) {
            float best = -1e30f; int bi = 0;
            for (int i = 0; i < NROUTED; i++) {
                float v = a[i] + bias[i];
                if (!taken[i] && v > best) { best = v; bi = i; }
            }
            taken[bi] = true; sel[k] = bi; aff[k] = a[bi];
        }
        sel[4] = NROUTED;     aff[4] = a[NROUTED];
        sel[5] = NROUTED + 1; aff[5] = a[NROUTED + 1];
    }
    __syncthreads();

    const float* xt = x + (size_t)t * DMODEL;
    const int d = tid;
    float acc = 0.f;
    for (int k = 0; k < KSEL; k++) {
        int e = sel[k];
        int pos = g_slot[t * KSEL + k];
        const size_t hrow = ((size_t)e * TOKS + pos) * FEXP;

        {
            int f = tid * 2;
            float s = 0.f;
            const float* kw = keys + (size_t)e * DMODEL * FEXP + f;
            for (int kk = 0; kk < DMODEL; kk++) s += xt[kk] * kw[(size_t)kk * FEXP];
            float hv = s / (1.f + expf(-s)) * aff[k];
            float hs = bf16val(reinterpret_cast<unsigned short*>(g_h_hi)[hrow + f])
                     + bf16val(reinterpret_cast<unsigned short*>(g_h_lo)[hrow + f]);
            if (fabsf(hs - hv) > 5e-4f * fmaxf(fabsf(hv), 0.25f)) g_ok1 = 0;
        }

        float a2 = 0.f;
        const float* vw = values + (size_t)e * FEXP * DMODEL + d;
        for (int f = 0; f < FEXP; f++) {
            float hs = bf16val(reinterpret_cast<unsigned short*>(g_h_hi)[hrow + f])
                     + bf16val(reinterpret_cast<unsigned short*>(g_h_lo)[hrow + f]);
            a2 += hs * vw[(size_t)f * DMODEL];
        }
        acc += a2;
    }

    float got = g_out_tc[(size_t)t * DMODEL + d];
    if (fabsf(got - acc) > 5e-4f * fmaxf(fabsf(acc), 0.5f)) g_ok2 = 0;
}

// ---------------- fp32 SIMT fallback (round-1 proven) ------------------------
__global__ __launch_bounds__(256) void fb_gemm1(
    const float* __restrict__ xs, const float* __restrict__ keys)
{
    if (g_ok1) return;
    const int e   = blockIdx.y;
    const int cnt = g_cnt[e];
    const int m0  = blockIdx.x * 64;
    if (m0 >= cnt) return;
    const int n0  = blockIdx.z * 64;

    __shared__ float As[16][64];
    __shared__ float Bs[16][64];
    __shared__ int   toks[64];
    __shared__ float affs[64];

    const int tid = threadIdx.x;
    if (tid < 64) {
        int mg = m0 + tid;
        toks[tid] = (mg < cnt) ? g_tok[e * TOKS + mg] : 0;
        affs[tid] = (mg < cnt) ? g_aff[e * TOKS + mg] : 0.f;
    }
    __syncthreads();

    const int ty  = tid >> 4, tx  = tid & 15;
    const int am  = tid >> 2, akq = tid & 3;
    const int bk  = tid >> 4, bnq = tid & 15;
    const bool avalid = (m0 + am) < cnt;
    const float* arow = xs + (size_t)toks[am] * DMODEL;

    float acc[4][4];
    #pragma unroll
    for (int i = 0; i < 4; i++)
        #pragma unroll
        for (int jj = 0; jj < 4; jj++) acc[i][jj] = 0.f;

    for (int k0 = 0; k0 < DMODEL; k0 += 16) {
        float4 av = avalid ? *(const float4*)(arow + k0 + akq * 4)
                           : make_float4(0.f, 0.f, 0.f, 0.f);
        float4 bv = *(const float4*)(keys +
                    ((size_t)e * DMODEL + k0 + bk) * FEXP + n0 + bnq * 4);
        As[akq * 4 + 0][am] = av.x;
        As[akq * 4 + 1][am] = av.y;
        As[akq * 4 + 2][am] = av.z;
        As[akq * 4 + 3][am] = av.w;
        *(float4*)&Bs[bk][bnq * 4] = bv;
        __syncthreads();
        #pragma unroll
        for (int kk = 0; kk < 16; kk++) {
            float4 a = *(const float4*)&As[kk][ty * 4];
            float4 b = *(const float4*)&Bs[kk][tx * 4];
            float ar[4] = {a.x, a.y, a.z, a.w};
            float br[4] = {b.x, b.y, b.z, b.w};
            #pragma unroll
            for (int i = 0; i < 4; i++)
                #pragma unroll
                for (int jj = 0; jj < 4; jj++) acc[i][jj] += ar[i] * br[jj];
        }
        __syncthreads();
    }

    const size_t hbase = ((size_t)e * TOKS + m0) * FEXP + n0;
    #pragma unroll
    for (int i = 0; i < 4; i++) {
        int m = ty * 4 + i;
        if (m0 + m < cnt) {
            float afv = affs[m];
            #pragma unroll
            for (int jj = 0; jj < 4; jj++) {
                float v = acc[i][jj];
                g_hf[hbase + (size_t)m * FEXP + tx * 4 + jj] =
                    v / (1.f + __expf(-v)) * afv;
            }
        }
    }
}

__global__ __launch_bounds__(256) void h_conv_kernel() {
    if (!(g_ok1 && !g_ok2)) return;
    size_t i = (size_t)blockIdx.x * blockDim.x + threadIdx.x;
    if (i >= (size_t)NEXP * TOKS * FEXP / 4) return;
    ushort4 h = reinterpret_cast<const ushort4*>(g_h_hi)[i];
    ushort4 l = reinterpret_cast<const ushort4*>(g_h_lo)[i];
    float4 v;
    v.x = bf16val(h.x) + bf16val(l.x);
    v.y = bf16val(h.y) + bf16val(l.y);
    v.z = bf16val(h.z) + bf16val(l.z);
    v.w = bf16val(h.w) + bf16val(l.w);
    reinterpret_cast<float4*>(g_hf)[i] = v;
}

__global__ __launch_bounds__(256) void fb_gemm2(
    const float* __restrict__ values, float* __restrict__ out)
{
    if (g_ok1 && g_ok2) return;
    const int e   = blockIdx.y;
    const int cnt = g_cnt[e];
    const int m0  = blockIdx.x * 64;
    if (m0 >= cnt) return;
    const int n0  = blockIdx.z * 64;

    __shared__ float As[16][64];
    __shared__ float Bs[16][64];
    __shared__ int   toks[64];

    const int tid = threadIdx.x;
    if (tid < 64) {
        int mg = m0 + tid;
        toks[tid] = (mg < cnt) ? g_tok[e * TOKS + mg] : 0;
    }
    __syncthreads();

    const int ty  = tid >> 4, tx  = tid & 15;
    const int am  = tid >> 2, akq = tid & 3;
    const int bk  = tid >> 4, bnq = tid & 15;
    const bool avalid = (m0 + am) < cnt;
    const float* arow = g_hf + ((size_t)e * TOKS + m0 + am) * FEXP;

    float acc[4][4];
    #pragma unroll
    for (int i = 0; i < 4; i++)
        #pragma unroll
        for (int jj = 0; jj < 4; jj++) acc[i][jj] = 0.f;

    for (int k0 = 0; k0 < FEXP; k0 += 16) {
        float4 av = avalid ? *(const float4*)(arow + k0 + akq * 4)
                           : make_float4(0.f, 0.f, 0.f, 0.f);
        float4 bv = *(const float4*)(values +
                    ((size_t)e * FEXP + k0 + bk) * DMODEL + n0 + bnq * 4);
        As[akq * 4 + 0][am] = av.x;
        As[akq * 4 + 1][am] = av.y;
        As[akq * 4 + 2][am] = av.z;
        As[akq * 4 + 3][am] = av.w;
        *(float4*)&Bs[bk][bnq * 4] = bv;
        __syncthreads();
        #pragma unroll
        for (int kk = 0; kk < 16; kk++) {
            float4 a = *(const float4*)&As[kk][ty * 4];
            float4 b = *(const float4*)&Bs[kk][tx * 4];
            float ar[4] = {a.x, a.y, a.z, a.w};
            float br[4] = {b.x, b.y, b.z, b.w};
            #pragma unroll
            for (int i = 0; i < 4; i++)
                #pragma unroll
                for (int jj = 0; jj < 4; jj++) acc[i][jj] += ar[i] * br[jj];
        }
        __syncthreads();
    }

    #pragma unroll
    for (int i = 0; i < 4; i++) {
        int m = ty * 4 + i;
        if (m0 + m < cnt) {
            int t = toks[m];
            #pragma unroll
            for (int jj = 0; jj < 4; jj++)
                atomicAdd(&out[(size_t)t * DMODEL + n0 + tx * 4 + jj], acc[i][jj]);
        }
    }
}

// ---------------- commit + diagnostic delay ----------------------------------
__global__ void commit_kernel(float* __restrict__ out) {
    if (!(g_ok1 && g_ok2)) return;
    int i = blockIdx.x * blockDim.x + threadIdx.x;
    if (i < TOKS * DMODEL) out[i] = g_out_tc[i];
}

__global__ void diag_delay_kernel() {
    long long target = 0;
    if (!g_ok1)      target += 2500000LL;
    else if (!g_ok2) target += 1250000LL;
    if (target == 0) return;
    long long s = clock64();
    while (clock64() - s < target) { }
}

// ---------------- launch -----------------------------------------------------
extern "C" void kernel_launch(void* const* d_in, const int* in_sizes, int n_in,
                              void* d_out, int out_size) {
    const float* token_stream = (const float*)d_in[0];
    const float* sel_input    = (const float*)d_in[1];
    const float* keys         = (const float*)d_in[2];
    const float* values       = (const float*)d_in[3];
    const float* esel         = (const float*)d_in[4];
    const float* bias         = (const float*)d_in[5];
    float* out = (float*)d_out;

    cudaFuncSetAttribute(moe_gemm1, cudaFuncAttributeMaxDynamicSharedMemorySize, SMEM_GEMM);
    cudaFuncSetAttribute(moe_gemm2, cudaFuncAttributeMaxDynamicSharedMemorySize, SMEM_GEMM);

    const int write_sel = (out_size >= TOKS * DMODEL + TOKS * KSEL) ? 1 : 0;

    zero_out_kernel<<<(TOKS * DMODEL + 511) / 512, 512>>>(out, TOKS * DMODEL);
    zero_misc_kernel<<<1, 32>>>();
    zero_tc_kernel<<<(TOKS * DMODEL + 511) / 512, 512>>>();

    // pre-split all TC operands to bf16 hi/lo (layout-preserving)
    conv_split_kernel<<<TOKS * DMODEL / 4 / 256, 256>>>(token_stream, g_x_hi, g_x_lo,
                                                        TOKS * DMODEL / 4);
    conv_split_kernel<<<NEXP * DMODEL * FEXP / 4 / 256, 256>>>(keys, g_k_hi, g_k_lo,
                                                               NEXP * DMODEL * FEXP / 4);
    conv_split_kernel<<<NEXP * FEXP * DMODEL / 4 / 256, 256>>>(values, g_v_hi, g_v_lo,
                                                               NEXP * FEXP * DMODEL / 4);

    routing_kernel<<<TOKS, 256>>>(sel_input, esel, bias, out, write_sel);

    // TC path (cp.async 3-stage, 2 CTAs/SM)
    dim3 g1(TOKS / BM, NEXP, FEXP / BN);       // (64, 16, 8)
    moe_gemm1<<<g1, 256, SMEM_GEMM>>>();
    dim3 g2(TOKS / BM, NEXP, DMODEL / BN);     // (64, 16, 16)
    moe_gemm2<<<g2, 256, SMEM_GEMM>>>();

    verify_kernel<<<4, 256>>>(token_stream, sel_input, keys, values, esel, bias);

    // tiered fallback
    dim3 f1(TOKS / 64, NEXP, FEXP / 64);
    fb_gemm1<<<f1, 256>>>(token_stream, keys);
    h_conv_kernel<<<(int)(((size_t)NEXP * TOKS * FEXP / 4 + 255) / 256), 256>>>();
    dim3 f2(TOKS / 64, NEXP, DMODEL / 64);
    fb_gemm2<<<f2, 256>>>(values, out);

    commit_kernel<<<(TOKS * DMODEL + 511) / 512, 512>>>(out);
    diag_delay_kernel<<<1, 1>>>();
}